// round 13
// baseline (speedup 1.0000x reference)
#include <cuda_runtime.h>
#include <cuda_fp16.h>
#include <cstdint>

#define NN 100000
#define NE 1600000
#define NG 512
#define FIN 20
#define HID 128
#define OUTF 64
#define NSCAN_BLK ((NN + 1023) / 1024)   // 98
#define PRE_ZBLK ((NN + 255) / 256)      // 392 blocks zero g_deg
#define PRE_WBLK 128                     // 128 blocks convert weights

// ---------------- scratch (device globals; no allocation allowed) ----------------
__device__ __align__(16) __half g_x16[(size_t)NN * 32];    // x * dinv[row], fp16, rows padded to 64B
__device__ __align__(16) __half g_h[(size_t)NN * HID];     // node features (post relu), fp16
__device__ __align__(16) __half g_xw[(size_t)NN * HID];    // gemm output * dinv[row], fp16
__device__ __align__(16) __half g_Wt[2][HID * HID];        // W2^T, W3^T in fp16 (n-major)
__device__ float g_dinv[NN];
__device__ int   g_deg[NN];                                // EDGE-only degree (self loop excluded)
__device__ int   g_rowptr[NN + 1];
__device__ int   g_cursor[NN];
__device__ int   g_col[NE];                                // CSR without self loops
__device__ int   g_part[NSCAN_BLK + 32];
__device__ int   g_gcnt[NG];
__device__ int   g_gstart[NG + 1];
__device__ int   g_is64;

// PDL: trigger dependent launch immediately (its blocks pre-launch and park at
// their wait); griddepcontrol.wait returns only after the previous grid has
// fully completed and its memory is visible -> ordering identical to serial.
#define PDL_TRIGGER() asm volatile("griddepcontrol.launch_dependents;")
#define PDL_WAIT()    asm volatile("griddepcontrol.wait;" ::: "memory")

// dtype-agnostic index load (edge_index/batch may be int32 or int64)
__device__ __forceinline__ int load_idx(const void* p, int is64, long long i) {
    if (is64) return (int)((const long long*)p)[i];
    return ((const int*)p)[i];
}

// ---------------- mma / ldmatrix wrappers ----------------
__device__ __forceinline__ void ldsm_x4(uint32_t addr, uint32_t& r0, uint32_t& r1,
                                        uint32_t& r2, uint32_t& r3) {
    asm volatile("ldmatrix.sync.aligned.m8n8.x4.shared.b16 {%0,%1,%2,%3}, [%4];"
                 : "=r"(r0), "=r"(r1), "=r"(r2), "=r"(r3) : "r"(addr));
}
__device__ __forceinline__ void ldsm_x2(uint32_t addr, uint32_t& r0, uint32_t& r1) {
    asm volatile("ldmatrix.sync.aligned.m8n8.x2.shared.b16 {%0,%1}, [%2];"
                 : "=r"(r0), "=r"(r1) : "r"(addr));
}
__device__ __forceinline__ void mma16816(float* c, uint32_t a0, uint32_t a1, uint32_t a2,
                                         uint32_t a3, uint32_t b0, uint32_t b1) {
    asm volatile(
        "mma.sync.aligned.m16n8k16.row.col.f32.f16.f16.f32 "
        "{%0,%1,%2,%3},{%4,%5,%6,%7},{%8,%9},{%0,%1,%2,%3};"
        : "+f"(c[0]), "+f"(c[1]), "+f"(c[2]), "+f"(c[3])
        : "r"(a0), "r"(a1), "r"(a2), "r"(a3), "r"(b0), "r"(b1));
}

// ---------------- fused prologue: zero deg/gcnt + dtype detect + weight convert ----------------
// blocks [0, PRE_ZBLK): zero g_deg / g_gcnt, block 0 thread 0 detects dtype
// blocks [PRE_ZBLK, PRE_ZBLK+PRE_WBLK): W2/W3 -> fp16 transposed g_Wt
__global__ void k_pre(const float* __restrict__ W2, const float* __restrict__ W3,
                      const int* __restrict__ ei32) {
    PDL_TRIGGER();
    int b = blockIdx.x, t = threadIdx.x;
    if (b < PRE_ZBLK) {
        int i = b * 256 + t;
        if (i < NN) g_deg[i] = 0;
        if (i < NG) g_gcnt[i] = 0;
        if (i == 0) {
            int z = 0;
            #pragma unroll
            for (int q = 1; q < 64; q += 2) z |= ei32[q];
            g_is64 = (z == 0) ? 1 : 0;
        }
    } else {
        int id = (b - PRE_ZBLK) * 256 + t;      // 0..32767
        int w = id >> 14;
        int e = id & 16383;
        int n = e >> 7, k = e & 127;
        const float* W = w ? W3 : W2;
        g_Wt[w][n * HID + k] = __float2half_rn(W[k * HID + n]);
    }
}

// fused: edge-degree atomics (threads < NE) + graph-count atomics (threads NE..NE+NN)
__global__ void k_count(const void* __restrict__ ei, const void* __restrict__ batch) {
    PDL_TRIGGER();
    PDL_WAIT();
    int i = blockIdx.x * blockDim.x + threadIdx.x;
    int is64 = g_is64;
    if (i < NE) {
        atomicAdd(&g_deg[load_idx(ei, is64, (long long)NE + i)], 1);
    } else if (i < NE + NN) {
        atomicAdd(&g_gcnt[load_idx(batch, is64, i - NE)], 1);
    }
}

// ---------------- multi-block scan of g_deg -> g_rowptr/g_cursor (+dinv, +x conversion) ----------------
__global__ void k_scan_part() {
    PDL_TRIGGER();
    PDL_WAIT();
    int b = blockIdx.x, t = threadIdx.x;
    int base = b * 1024 + t * 4;
    int s = 0;
    #pragma unroll
    for (int i = 0; i < 4; i++) {
        int idx = base + i;
        if (idx < NN) s += g_deg[idx];
    }
    #pragma unroll
    for (int o = 16; o; o >>= 1) s += __shfl_down_sync(0xffffffffu, s, o);
    __shared__ int ws[8];
    if ((t & 31) == 0) ws[t >> 5] = s;
    __syncthreads();
    if (t == 0) {
        int tot = 0;
        #pragma unroll
        for (int i = 0; i < 8; i++) tot += ws[i];
        g_part[b] = tot;
    }
}

// fused: block 0 scans partials; block 1 scans graph counts
__global__ void k_scan_mid() {
    PDL_TRIGGER();
    PDL_WAIT();
    int t = threadIdx.x, lane = t & 31, w = t >> 5;
    if (blockIdx.x == 0) {
        __shared__ int wsum[4];
        if (t < 128) {
            int v = (t < NSCAN_BLK) ? g_part[t] : 0;
            int x = v;
            #pragma unroll
            for (int o = 1; o < 32; o <<= 1) {
                int y = __shfl_up_sync(0xffffffffu, x, o);
                if (lane >= o) x += y;
            }
            if (lane == 31) wsum[w] = x;
            __syncthreads();
            if (t == 0) {
                int run = 0;
                #pragma unroll
                for (int i = 0; i < 4; i++) { int tmp = wsum[i]; wsum[i] = run; run += tmp; }
            }
            __syncthreads();
            if (t < NSCAN_BLK) g_part[t] = x - v + wsum[w];
            if (t == 0) g_rowptr[NN] = NE;
        } else {
            __syncthreads();
            __syncthreads();
        }
    } else {
        __shared__ int wsum[16];
        int v = g_gcnt[t];
        int x = v;
        #pragma unroll
        for (int o = 1; o < 32; o <<= 1) {
            int y = __shfl_up_sync(0xffffffffu, x, o);
            if (lane >= o) x += y;
        }
        if (lane == 31) wsum[w] = x;
        __syncthreads();
        if (w == 0 && lane < 16) {
            int s = wsum[lane];
            #pragma unroll
            for (int o = 1; o < 16; o <<= 1) {
                int y = __shfl_up_sync(0xffffu, s, o);
                if (lane >= o) s += y;
            }
            wsum[lane] = s;
        }
        __syncthreads();
        int incl = x + (w > 0 ? wsum[w - 1] : 0);
        g_gstart[t] = incl - v;
        if (t == 0) g_gstart[NG] = wsum[15];
    }
}

// final scan pass + dinv + x->fp16 prescale (fused, dinv is in-register here)
__global__ void k_scan_final(const float* __restrict__ x) {
    PDL_TRIGGER();
    PDL_WAIT();
    int b = blockIdx.x, t = threadIdx.x, lane = t & 31, w = t >> 5;
    int base = b * 1024 + t * 4;
    int v[4];
    int tsum = 0;
    #pragma unroll
    for (int i = 0; i < 4; i++) {
        v[i] = (base + i < NN) ? g_deg[base + i] : 0;
        tsum += v[i];
    }
    int xs = tsum;
    #pragma unroll
    for (int o = 1; o < 32; o <<= 1) {
        int y = __shfl_up_sync(0xffffffffu, xs, o);
        if (lane >= o) xs += y;
    }
    __shared__ int wsum[8];
    if (lane == 31) wsum[w] = xs;
    __syncthreads();
    if (t == 0) {
        int run = 0;
        #pragma unroll
        for (int i = 0; i < 8; i++) { int tmp = wsum[i]; wsum[i] = run; run += tmp; }
    }
    __syncthreads();
    int run = xs - tsum + wsum[w] + g_part[b];
    #pragma unroll
    for (int i = 0; i < 4; i++) {
        int row = base + i;
        if (row < NN) {
            g_rowptr[row] = run;
            g_cursor[row] = run;
            float dn = rsqrtf((float)(v[i] + 1));   // +1 self loop
            g_dinv[row] = dn;
            run += v[i];
            // fused x conversion: f32 row (80B, float4-aligned) -> prescaled fp16 (64B)
            const float4* xr = (const float4*)(x + (size_t)row * FIN);
            float f[20];
            #pragma unroll
            for (int q = 0; q < 5; q++) {
                float4 v4 = xr[q];
                f[q * 4] = v4.x; f[q * 4 + 1] = v4.y; f[q * 4 + 2] = v4.z; f[q * 4 + 3] = v4.w;
            }
            __align__(16) __half2 h[16];
            #pragma unroll
            for (int c = 0; c < 10; c++) h[c] = __floats2half2_rn(f[2 * c] * dn, f[2 * c + 1] * dn);
            #pragma unroll
            for (int c = 10; c < 16; c++) h[c] = __floats2half2_rn(0.f, 0.f);
            uint4* dst = (uint4*)&g_x16[(size_t)row * 32];
            const uint4* src = (const uint4*)h;
            dst[0] = src[0]; dst[1] = src[1]; dst[2] = src[2]; dst[3] = src[3];
        }
    }
}

// one edge per thread; self loops NOT scattered
__global__ void k_scatter(const void* __restrict__ ei) {
    PDL_TRIGGER();
    PDL_WAIT();
    int e = blockIdx.x * blockDim.x + threadIdx.x;
    if (e >= NE) return;
    int is64 = g_is64;
    int s = load_idx(ei, is64, e);
    int d = load_idx(ei, is64, (long long)NE + e);
    int pos = atomicAdd(&g_cursor[d], 1);
    g_col[pos] = s;
}

// ---------------- fused layer 1: aggregate prescaled fp16 x + GEMM + bias + relu ----------------
// block = 256 threads, 64 nodes. Warp w aggregates nodes w*8..w*8+7 into smem,
// then the whole block runs the 20x128 GEMM from smem. Wsh load is pre-wait
// (W1 is an immutable harness input) and overlaps the scatter tail under PDL.
__global__ void k_aggx_gemm1(const float* __restrict__ W1, const float* __restrict__ b1) {
    PDL_TRIGGER();
    __shared__ __align__(16) float Wsh[FIN * HID];  // 10 KB
    __shared__ float xsh[64 * FIN];                 // 5 KB
    int t = threadIdx.x;
    int bn = blockIdx.x * 64;
    for (int i = t; i < FIN * HID; i += 256) Wsh[i] = W1[i];   // input: safe pre-wait
    PDL_WAIT();

    int w = t >> 5, lane = t & 31;
    // aggregation phase: warp per node, 8 nodes per warp
    for (int ni = 0; ni < 8; ni++) {
        int node = bn + w * 8 + ni;
        float2 acc = make_float2(0.f, 0.f);
        if (node < NN) {
            int r = g_rowptr[node], e = g_rowptr[node + 1];
            if (lane < 16)
                acc = __half22float2(*(const __half2*)&g_x16[(size_t)node * 32 + lane * 2]);
            int j = r;
            for (; j + 2 <= e; j += 2) {
                int sA = g_col[j], sB = g_col[j + 1];
                if (lane < 16) {
                    float2 fA = __half22float2(*(const __half2*)&g_x16[(size_t)sA * 32 + lane * 2]);
                    float2 fB = __half22float2(*(const __half2*)&g_x16[(size_t)sB * 32 + lane * 2]);
                    acc.x += fA.x + fB.x; acc.y += fA.y + fB.y;
                }
            }
            if (j < e) {
                int s = g_col[j];
                if (lane < 16) {
                    float2 f = __half22float2(*(const __half2*)&g_x16[(size_t)s * 32 + lane * 2]);
                    acc.x += f.x; acc.y += f.y;
                }
            }
            if (lane < 10) {
                float dn = g_dinv[node];
                xsh[(w * 8 + ni) * FIN + lane * 2]     = acc.x * dn;
                xsh[(w * 8 + ni) * FIN + lane * 2 + 1] = acc.y * dn;
            }
        } else if (lane < 10) {
            xsh[(w * 8 + ni) * FIN + lane * 2]     = 0.f;
            xsh[(w * 8 + ni) * FIN + lane * 2 + 1] = 0.f;
        }
    }
    __syncthreads();

    // GEMM phase: warp g handles rows g*8..g*8+7, lanes cover 128 cols x4
    int c4 = lane * 4;
    float4 acc[8];
    #pragma unroll
    for (int i = 0; i < 8; i++) acc[i] = make_float4(0.f, 0.f, 0.f, 0.f);
    for (int k = 0; k < FIN; k++) {
        float4 wv = *(const float4*)&Wsh[k * HID + c4];
        #pragma unroll
        for (int i = 0; i < 8; i++) {
            float xv = xsh[(w * 8 + i) * FIN + k];
            acc[i].x += wv.x * xv; acc[i].y += wv.y * xv;
            acc[i].z += wv.z * xv; acc[i].w += wv.w * xv;
        }
    }
    float4 bb = *(const float4*)&b1[c4];
    #pragma unroll
    for (int i = 0; i < 8; i++) {
        int n = bn + w * 8 + i;
        if (n < NN) {
            float ox = fmaxf(acc[i].x + bb.x, 0.f), oy = fmaxf(acc[i].y + bb.y, 0.f);
            float oz = fmaxf(acc[i].z + bb.z, 0.f), ow = fmaxf(acc[i].w + bb.w, 0.f);
            __half2* p = (__half2*)&g_h[(size_t)n * HID + c4];
            p[0] = __floats2half2_rn(ox, oy);
            p[1] = __floats2half2_rn(oz, ow);
        }
    }
}

// ---------------- hidden GEMM: g_h[N,128] @ W[128,128], * dinv[row] -> g_xw fp16 ----------------
__global__ __launch_bounds__(256, 2) void k_gemm_mma(int widx) {
    PDL_TRIGGER();
    PDL_WAIT();
    __shared__ __align__(16) __half Ash[64 * HID];    // 16 KB, swizzled
    __shared__ __align__(16) __half Wsh[HID * HID];   // 32 KB, swizzled
    int t = threadIdx.x;
    int bn = blockIdx.x * 64;

    for (int i = t; i < 64 * 16; i += 256) {
        int row = i >> 4, ch = i & 15;
        int gr = bn + row;
        uint4 v = make_uint4(0u, 0u, 0u, 0u);
        if (gr < NN) v = *(const uint4*)&g_h[(size_t)gr * HID + ch * 8];
        *(uint4*)((char*)Ash + row * 256 + ((ch ^ (row & 7)) << 4)) = v;
    }
    const __half* Wt = g_Wt[widx];
    for (int i = t; i < 128 * 16; i += 256) {
        int row = i >> 4, ch = i & 15;
        uint4 v = *(const uint4*)&Wt[(size_t)row * HID + ch * 8];
        *(uint4*)((char*)Wsh + row * 256 + ((ch ^ (row & 7)) << 4)) = v;
    }
    __syncthreads();

    int w = t >> 5, lane = t & 31;
    int mb = (w & 3) * 16;
    int nb = (w >> 2) * 8;
    uint32_t AshB = (uint32_t)__cvta_generic_to_shared(Ash);
    uint32_t WshB = (uint32_t)__cvta_generic_to_shared(Wsh);

    float c[8][4];
    #pragma unroll
    for (int i = 0; i < 8; i++)
        #pragma unroll
        for (int j = 0; j < 4; j++) c[i][j] = 0.f;

    int sel = lane >> 3, r8 = lane & 7;
    #pragma unroll
    for (int ks = 0; ks < 8; ks++) {
        int arow = mb + r8 + ((sel & 1) << 3);
        int ach = ks * 2 + (sel >> 1);
        uint32_t a0, a1, a2, a3;
        ldsm_x4(AshB + arow * 256 + ((ach ^ (arow & 7)) << 4), a0, a1, a2, a3);
        int bch = ks * 2 + ((lane >> 3) & 1);
        #pragma unroll
        for (int nt = 0; nt < 8; nt++) {
            int brow = (nb + nt) * 8 + r8;
            uint32_t b0, b1;
            ldsm_x2(WshB + brow * 256 + ((bch ^ (brow & 7)) << 4), b0, b1);
            mma16816(c[nt], a0, a1, a2, a3, b0, b1);
        }
    }

    int r1 = bn + mb + (lane >> 2);
    int r2 = r1 + 8;
    float s1 = (r1 < NN) ? g_dinv[r1] : 0.f;
    float s2 = (r2 < NN) ? g_dinv[r2] : 0.f;
    #pragma unroll
    for (int nt = 0; nt < 8; nt++) {
        int col = (nb + nt) * 8 + (lane & 3) * 2;
        if (r1 < NN)
            *(__half2*)&g_xw[(size_t)r1 * HID + col] = __floats2half2_rn(c[nt][0] * s1, c[nt][1] * s1);
        if (r2 < NN)
            *(__half2*)&g_xw[(size_t)r2 * HID + col] = __floats2half2_rn(c[nt][2] * s2, c[nt][3] * s2);
    }
}

// ---------------- aggregation (hidden layers) ----------------
// g_h[d] = relu( dinv[d] * ( xw[d] + sum_e xw[s] ) + b ), xw scaled by dinv[row]
__global__ void k_agg_h(const float* __restrict__ bias) {
    PDL_TRIGGER();
    PDL_WAIT();
    int wid = (blockIdx.x * blockDim.x + threadIdx.x) >> 5;
    int lane = threadIdx.x & 31;
    if (wid >= NN) return;
    int r = g_rowptr[wid], e = g_rowptr[wid + 1];
    uint2 v0 = *(const uint2*)&g_xw[(size_t)wid * HID + lane * 4];  // self loop
    float2 f0 = __half22float2(*(__half2*)&v0.x);
    float2 f1 = __half22float2(*(__half2*)&v0.y);
    float4 acc = make_float4(f0.x, f0.y, f1.x, f1.y);
    int j = r;
    for (; j + 2 <= e; j += 2) {
        int sA = g_col[j], sB = g_col[j + 1];
        uint2 vA = *(const uint2*)&g_xw[(size_t)sA * HID + lane * 4];
        uint2 vB = *(const uint2*)&g_xw[(size_t)sB * HID + lane * 4];
        float2 a0 = __half22float2(*(__half2*)&vA.x);
        float2 a1 = __half22float2(*(__half2*)&vA.y);
        float2 b0 = __half22float2(*(__half2*)&vB.x);
        float2 b1 = __half22float2(*(__half2*)&vB.y);
        acc.x += a0.x + b0.x; acc.y += a0.y + b0.y;
        acc.z += a1.x + b1.x; acc.w += a1.y + b1.y;
    }
    if (j < e) {
        int s = g_col[j];
        uint2 v = *(const uint2*)&g_xw[(size_t)s * HID + lane * 4];
        float2 a0 = __half22float2(*(__half2*)&v.x);
        float2 a1 = __half22float2(*(__half2*)&v.y);
        acc.x += a0.x; acc.y += a0.y; acc.z += a1.x; acc.w += a1.y;
    }
    float dn = g_dinv[wid];
    float4 b = *(const float4*)&bias[lane * 4];
    float ox = fmaxf(acc.x * dn + b.x, 0.f), oy = fmaxf(acc.y * dn + b.y, 0.f);
    float oz = fmaxf(acc.z * dn + b.z, 0.f), ow = fmaxf(acc.w * dn + b.w, 0.f);
    __half2* p = (__half2*)&g_h[(size_t)wid * HID + lane * 4];
    p[0] = __floats2half2_rn(ox, oy);
    p[1] = __floats2half2_rn(oz, ow);
}

// ---------------- mean-pool + output head ----------------
__global__ void k_pool(const float* __restrict__ Wout, const float* __restrict__ bout,
                       float* __restrict__ out) {
    PDL_TRIGGER();
    PDL_WAIT();
    int gg = blockIdx.x;
    int t = threadIdx.x;  // 128
    int st = g_gstart[gg], en = g_gstart[gg + 1];
    float acc = 0.f;
    for (int n = st; n < en; n++) acc += __half2float(g_h[(size_t)n * HID + t]);
    __shared__ float pooled[HID];
    float cnt = (float)(en - st);
    if (cnt < 1.f) cnt = 1.f;
    pooled[t] = acc / cnt;
    __syncthreads();
    if (t < OUTF) {
        float o = bout[t];
        #pragma unroll 8
        for (int k = 0; k < HID; k++) o += pooled[k] * Wout[k * OUTF + t];
        out[(size_t)gg * OUTF + t] = o;
    }
}

// ---------------- PDL launch helper ----------------
template <typename F, typename... Args>
static inline void pdl_launch(F kern, int grid, int block, Args... args) {
    cudaLaunchConfig_t cfg = {};
    cfg.gridDim = dim3((unsigned)grid, 1, 1);
    cfg.blockDim = dim3((unsigned)block, 1, 1);
    cfg.stream = 0;  // legacy default stream (same one <<<>>> used)
    cudaLaunchAttribute attr[1];
    attr[0].id = cudaLaunchAttributeProgrammaticStreamSerialization;
    attr[0].val.programmaticStreamSerializationAllowed = 1;
    cfg.attrs = attr;
    cfg.numAttrs = 1;
    cudaLaunchKernelEx(&cfg, kern, args...);
}

// ---------------- launcher ----------------
extern "C" void kernel_launch(void* const* d_in, const int* in_sizes, int n_in,
                              void* d_out, int out_size) {
    const float* x     = (const float*)d_in[0];
    const void*  ei    = d_in[1];
    const void*  batch = d_in[2];
    const float* W1 = (const float*)d_in[3];  const float* b1 = (const float*)d_in[4];
    const float* W2 = (const float*)d_in[5];  const float* b2 = (const float*)d_in[6];
    const float* W3 = (const float*)d_in[7];  const float* b3 = (const float*)d_in[8];
    const float* Wout = (const float*)d_in[9]; const float* bout = (const float*)d_in[10];
    float* out = (float*)d_out;

    const int agg_blocks = (NN + 7) / 8;     // warp per node
    const int mma_blocks = (NN + 63) / 64;

    pdl_launch(k_pre, PRE_ZBLK + PRE_WBLK, 256, W2, W3, (const int*)ei);
    pdl_launch(k_count, (NE + NN + 255) / 256, 256, ei, batch);
    pdl_launch(k_scan_part, NSCAN_BLK, 256);
    pdl_launch(k_scan_mid, 2, 512);
    pdl_launch(k_scan_final, NSCAN_BLK, 256, x);
    pdl_launch(k_scatter, (NE + 255) / 256, 256, ei);

    // layer 1 (fused agg + gemm)
    pdl_launch(k_aggx_gemm1, (NN + 63) / 64, 256, W1, b1);
    // layer 2
    pdl_launch(k_gemm_mma, mma_blocks, 256, 0);
    pdl_launch(k_agg_h, agg_blocks, 256, b2);
    // layer 3
    pdl_launch(k_gemm_mma, mma_blocks, 256, 1);
    pdl_launch(k_agg_h, agg_blocks, 256, b3);

    // pool + head
    pdl_launch(k_pool, NG, HID, Wout, bout, out);
}

// round 14
// speedup vs baseline: 1.0739x; 1.0739x over previous
#include <cuda_runtime.h>
#include <cuda_fp16.h>
#include <cstdint>

#define NN 100000
#define NE 1600000
#define NG 512
#define FIN 20
#define HID 128
#define OUTF 64
#define NSCAN_BLK ((NN + 1023) / 1024)   // 98
#define PRE_ZBLK ((NN + 255) / 256)      // 392 blocks zero g_deg
#define PRE_WBLK 128                     // 128 blocks convert weights

// ---------------- scratch (device globals; no allocation allowed) ----------------
__device__ __align__(16) __half g_x16[(size_t)NN * 32];    // x * dinv[row], fp16, rows padded to 64B
__device__ __align__(16) __half g_h[(size_t)NN * HID];     // node features (post relu), fp16
__device__ __align__(16) __half g_xw[(size_t)NN * HID];    // gemm output * dinv[row], fp16
__device__ __align__(16) __half g_Wt[2][HID * HID];        // W2^T, W3^T in fp16 (n-major)
__device__ float g_dinv[NN];
__device__ int   g_deg[NN];                                // EDGE-only degree (self loop excluded)
__device__ int   g_rowptr[NN + 1];
__device__ int   g_cursor[NN];
__device__ int   g_col[NE];                                // CSR without self loops
__device__ int   g_part[NSCAN_BLK + 32];
__device__ int   g_gcnt[NG];
__device__ int   g_gstart[NG + 1];
__device__ int   g_is64;

// dtype-agnostic index load (edge_index/batch may be int32 or int64)
__device__ __forceinline__ int load_idx(const void* p, int is64, long long i) {
    if (is64) return (int)((const long long*)p)[i];
    return ((const int*)p)[i];
}

// ---------------- mma / ldmatrix wrappers ----------------
__device__ __forceinline__ void ldsm_x4(uint32_t addr, uint32_t& r0, uint32_t& r1,
                                        uint32_t& r2, uint32_t& r3) {
    asm volatile("ldmatrix.sync.aligned.m8n8.x4.shared.b16 {%0,%1,%2,%3}, [%4];"
                 : "=r"(r0), "=r"(r1), "=r"(r2), "=r"(r3) : "r"(addr));
}
__device__ __forceinline__ void ldsm_x2(uint32_t addr, uint32_t& r0, uint32_t& r1) {
    asm volatile("ldmatrix.sync.aligned.m8n8.x2.shared.b16 {%0,%1}, [%2];"
                 : "=r"(r0), "=r"(r1) : "r"(addr));
}
__device__ __forceinline__ void mma16816(float* c, uint32_t a0, uint32_t a1, uint32_t a2,
                                         uint32_t a3, uint32_t b0, uint32_t b1) {
    asm volatile(
        "mma.sync.aligned.m16n8k16.row.col.f32.f16.f16.f32 "
        "{%0,%1,%2,%3},{%4,%5,%6,%7},{%8,%9},{%0,%1,%2,%3};"
        : "+f"(c[0]), "+f"(c[1]), "+f"(c[2]), "+f"(c[3])
        : "r"(a0), "r"(a1), "r"(a2), "r"(a3), "r"(b0), "r"(b1));
}

// ---------------- fused prologue: zero deg/gcnt + dtype detect + weight convert ----------------
__global__ void k_pre(const float* __restrict__ W2, const float* __restrict__ W3,
                      const int* __restrict__ ei32) {
    int b = blockIdx.x, t = threadIdx.x;
    if (b < PRE_ZBLK) {
        int i = b * 256 + t;
        if (i < NN) g_deg[i] = 0;
        if (i < NG) g_gcnt[i] = 0;
        if (i == 0) {
            int z = 0;
            #pragma unroll
            for (int q = 1; q < 64; q += 2) z |= ei32[q];
            g_is64 = (z == 0) ? 1 : 0;
        }
    } else {
        int id = (b - PRE_ZBLK) * 256 + t;      // 0..32767
        int w = id >> 14;
        int e = id & 16383;
        int n = e >> 7, k = e & 127;
        const float* W = w ? W3 : W2;
        g_Wt[w][n * HID + k] = __float2half_rn(W[k * HID + n]);
    }
}

// fused: edge-degree atomics (threads < NE) + graph-count atomics (threads NE..NE+NN)
__global__ void k_count(const void* __restrict__ ei, const void* __restrict__ batch) {
    int i = blockIdx.x * blockDim.x + threadIdx.x;
    int is64 = g_is64;
    if (i < NE) {
        atomicAdd(&g_deg[load_idx(ei, is64, (long long)NE + i)], 1);
    } else if (i < NE + NN) {
        atomicAdd(&g_gcnt[load_idx(batch, is64, i - NE)], 1);
    }
}

// ---------------- multi-block scan of g_deg -> g_rowptr/g_cursor (+dinv, +x conversion) ----------------
__global__ void k_scan_part() {
    int b = blockIdx.x, t = threadIdx.x;
    int base = b * 1024 + t * 4;
    int s = 0;
    #pragma unroll
    for (int i = 0; i < 4; i++) {
        int idx = base + i;
        if (idx < NN) s += g_deg[idx];
    }
    #pragma unroll
    for (int o = 16; o; o >>= 1) s += __shfl_down_sync(0xffffffffu, s, o);
    __shared__ int ws[8];
    if ((t & 31) == 0) ws[t >> 5] = s;
    __syncthreads();
    if (t == 0) {
        int tot = 0;
        #pragma unroll
        for (int i = 0; i < 8; i++) tot += ws[i];
        g_part[b] = tot;
    }
}

// fused: block 0 scans partials; block 1 scans graph counts
__global__ void k_scan_mid() {
    int t = threadIdx.x, lane = t & 31, w = t >> 5;
    if (blockIdx.x == 0) {
        __shared__ int wsum[4];
        if (t < 128) {
            int v = (t < NSCAN_BLK) ? g_part[t] : 0;
            int x = v;
            #pragma unroll
            for (int o = 1; o < 32; o <<= 1) {
                int y = __shfl_up_sync(0xffffffffu, x, o);
                if (lane >= o) x += y;
            }
            if (lane == 31) wsum[w] = x;
            __syncthreads();
            if (t == 0) {
                int run = 0;
                #pragma unroll
                for (int i = 0; i < 4; i++) { int tmp = wsum[i]; wsum[i] = run; run += tmp; }
            }
            __syncthreads();
            if (t < NSCAN_BLK) g_part[t] = x - v + wsum[w];
            if (t == 0) g_rowptr[NN] = NE;
        } else {
            __syncthreads();
            __syncthreads();
        }
    } else {
        __shared__ int wsum[16];
        int v = g_gcnt[t];
        int x = v;
        #pragma unroll
        for (int o = 1; o < 32; o <<= 1) {
            int y = __shfl_up_sync(0xffffffffu, x, o);
            if (lane >= o) x += y;
        }
        if (lane == 31) wsum[w] = x;
        __syncthreads();
        if (w == 0 && lane < 16) {
            int s = wsum[lane];
            #pragma unroll
            for (int o = 1; o < 16; o <<= 1) {
                int y = __shfl_up_sync(0xffffu, s, o);
                if (lane >= o) s += y;
            }
            wsum[lane] = s;
        }
        __syncthreads();
        int incl = x + (w > 0 ? wsum[w - 1] : 0);
        g_gstart[t] = incl - v;
        if (t == 0) g_gstart[NG] = wsum[15];
    }
}

// final scan pass + dinv + x->fp16 prescale (fused, dinv is in-register here)
__global__ void k_scan_final(const float* __restrict__ x) {
    int b = blockIdx.x, t = threadIdx.x, lane = t & 31, w = t >> 5;
    int base = b * 1024 + t * 4;
    int v[4];
    int tsum = 0;
    #pragma unroll
    for (int i = 0; i < 4; i++) {
        v[i] = (base + i < NN) ? g_deg[base + i] : 0;
        tsum += v[i];
    }
    int xs = tsum;
    #pragma unroll
    for (int o = 1; o < 32; o <<= 1) {
        int y = __shfl_up_sync(0xffffffffu, xs, o);
        if (lane >= o) xs += y;
    }
    __shared__ int wsum[8];
    if (lane == 31) wsum[w] = xs;
    __syncthreads();
    if (t == 0) {
        int run = 0;
        #pragma unroll
        for (int i = 0; i < 8; i++) { int tmp = wsum[i]; wsum[i] = run; run += tmp; }
    }
    __syncthreads();
    int run = xs - tsum + wsum[w] + g_part[b];
    #pragma unroll
    for (int i = 0; i < 4; i++) {
        int row = base + i;
        if (row < NN) {
            g_rowptr[row] = run;
            g_cursor[row] = run;
            float dn = rsqrtf((float)(v[i] + 1));   // +1 self loop
            g_dinv[row] = dn;
            run += v[i];
            // fused x conversion: f32 row (80B, float4-aligned) -> prescaled fp16 (64B)
            const float4* xr = (const float4*)(x + (size_t)row * FIN);
            float f[20];
            #pragma unroll
            for (int q = 0; q < 5; q++) {
                float4 v4 = xr[q];
                f[q * 4] = v4.x; f[q * 4 + 1] = v4.y; f[q * 4 + 2] = v4.z; f[q * 4 + 3] = v4.w;
            }
            __align__(16) __half2 h[16];
            #pragma unroll
            for (int c = 0; c < 10; c++) h[c] = __floats2half2_rn(f[2 * c] * dn, f[2 * c + 1] * dn);
            #pragma unroll
            for (int c = 10; c < 16; c++) h[c] = __floats2half2_rn(0.f, 0.f);
            uint4* dst = (uint4*)&g_x16[(size_t)row * 32];
            const uint4* src = (const uint4*)h;
            dst[0] = src[0]; dst[1] = src[1]; dst[2] = src[2]; dst[3] = src[3];
        }
    }
}

// one edge per thread; self loops NOT scattered
__global__ void k_scatter(const void* __restrict__ ei) {
    int e = blockIdx.x * blockDim.x + threadIdx.x;
    if (e >= NE) return;
    int is64 = g_is64;
    int s = load_idx(ei, is64, e);
    int d = load_idx(ei, is64, (long long)NE + e);
    int pos = atomicAdd(&g_cursor[d], 1);
    g_col[pos] = s;
}

// ---------------- fused layer 1: aggregate prescaled fp16 x + GEMM + bias + relu ----------------
__global__ void k_aggx_gemm1(const float* __restrict__ W1, const float* __restrict__ b1) {
    __shared__ __align__(16) float Wsh[FIN * HID];  // 10 KB
    __shared__ float xsh[64 * FIN];                 // 5 KB
    int t = threadIdx.x;
    int bn = blockIdx.x * 64;
    for (int i = t; i < FIN * HID; i += 256) Wsh[i] = W1[i];

    int w = t >> 5, lane = t & 31;
    // aggregation phase: warp per node, 8 nodes per warp, 4-wide MLP on gathers
    for (int ni = 0; ni < 8; ni++) {
        int node = bn + w * 8 + ni;
        float2 acc = make_float2(0.f, 0.f);
        if (node < NN) {
            int r = g_rowptr[node], e = g_rowptr[node + 1];
            if (lane < 16)
                acc = __half22float2(*(const __half2*)&g_x16[(size_t)node * 32 + lane * 2]);
            int j = r;
            for (; j + 4 <= e; j += 4) {
                int s0 = g_col[j], s1 = g_col[j + 1], s2 = g_col[j + 2], s3 = g_col[j + 3];
                if (lane < 16) {
                    float2 f0 = __half22float2(*(const __half2*)&g_x16[(size_t)s0 * 32 + lane * 2]);
                    float2 f1 = __half22float2(*(const __half2*)&g_x16[(size_t)s1 * 32 + lane * 2]);
                    float2 f2 = __half22float2(*(const __half2*)&g_x16[(size_t)s2 * 32 + lane * 2]);
                    float2 f3 = __half22float2(*(const __half2*)&g_x16[(size_t)s3 * 32 + lane * 2]);
                    acc.x += (f0.x + f1.x) + (f2.x + f3.x);
                    acc.y += (f0.y + f1.y) + (f2.y + f3.y);
                }
            }
            for (; j < e; j++) {
                int s = g_col[j];
                if (lane < 16) {
                    float2 f = __half22float2(*(const __half2*)&g_x16[(size_t)s * 32 + lane * 2]);
                    acc.x += f.x; acc.y += f.y;
                }
            }
            if (lane < 10) {
                float dn = g_dinv[node];
                xsh[(w * 8 + ni) * FIN + lane * 2]     = acc.x * dn;
                xsh[(w * 8 + ni) * FIN + lane * 2 + 1] = acc.y * dn;
            }
        } else if (lane < 10) {
            xsh[(w * 8 + ni) * FIN + lane * 2]     = 0.f;
            xsh[(w * 8 + ni) * FIN + lane * 2 + 1] = 0.f;
        }
    }
    __syncthreads();

    // GEMM phase: warp w handles rows w*8..w*8+7, lanes cover 128 cols x4
    int c4 = lane * 4;
    float4 acc[8];
    #pragma unroll
    for (int i = 0; i < 8; i++) acc[i] = make_float4(0.f, 0.f, 0.f, 0.f);
    for (int k = 0; k < FIN; k++) {
        float4 wv = *(const float4*)&Wsh[k * HID + c4];
        #pragma unroll
        for (int i = 0; i < 8; i++) {
            float xv = xsh[(w * 8 + i) * FIN + k];
            acc[i].x += wv.x * xv; acc[i].y += wv.y * xv;
            acc[i].z += wv.z * xv; acc[i].w += wv.w * xv;
        }
    }
    float4 bb = *(const float4*)&b1[c4];
    #pragma unroll
    for (int i = 0; i < 8; i++) {
        int n = bn + w * 8 + i;
        if (n < NN) {
            float ox = fmaxf(acc[i].x + bb.x, 0.f), oy = fmaxf(acc[i].y + bb.y, 0.f);
            float oz = fmaxf(acc[i].z + bb.z, 0.f), ow = fmaxf(acc[i].w + bb.w, 0.f);
            __half2* p = (__half2*)&g_h[(size_t)n * HID + c4];
            p[0] = __floats2half2_rn(ox, oy);
            p[1] = __floats2half2_rn(oz, ow);
        }
    }
}

// ---------------- hidden GEMM: g_h[N,128] @ W[128,128], * dinv[row] -> g_xw fp16 ----------------
__global__ __launch_bounds__(256, 2) void k_gemm_mma(int widx) {
    __shared__ __align__(16) __half Ash[64 * HID];    // 16 KB, swizzled
    __shared__ __align__(16) __half Wsh[HID * HID];   // 32 KB, swizzled
    int t = threadIdx.x;
    int bn = blockIdx.x * 64;

    for (int i = t; i < 64 * 16; i += 256) {
        int row = i >> 4, ch = i & 15;
        int gr = bn + row;
        uint4 v = make_uint4(0u, 0u, 0u, 0u);
        if (gr < NN) v = *(const uint4*)&g_h[(size_t)gr * HID + ch * 8];
        *(uint4*)((char*)Ash + row * 256 + ((ch ^ (row & 7)) << 4)) = v;
    }
    const __half* Wt = g_Wt[widx];
    for (int i = t; i < 128 * 16; i += 256) {
        int row = i >> 4, ch = i & 15;
        uint4 v = *(const uint4*)&Wt[(size_t)row * HID + ch * 8];
        *(uint4*)((char*)Wsh + row * 256 + ((ch ^ (row & 7)) << 4)) = v;
    }
    __syncthreads();

    int w = t >> 5, lane = t & 31;
    int mb = (w & 3) * 16;
    int nb = (w >> 2) * 8;
    uint32_t AshB = (uint32_t)__cvta_generic_to_shared(Ash);
    uint32_t WshB = (uint32_t)__cvta_generic_to_shared(Wsh);

    float c[8][4];
    #pragma unroll
    for (int i = 0; i < 8; i++)
        #pragma unroll
        for (int j = 0; j < 4; j++) c[i][j] = 0.f;

    int sel = lane >> 3, r8 = lane & 7;
    #pragma unroll
    for (int ks = 0; ks < 8; ks++) {
        int arow = mb + r8 + ((sel & 1) << 3);
        int ach = ks * 2 + (sel >> 1);
        uint32_t a0, a1, a2, a3;
        ldsm_x4(AshB + arow * 256 + ((ach ^ (arow & 7)) << 4), a0, a1, a2, a3);
        int bch = ks * 2 + ((lane >> 3) & 1);
        #pragma unroll
        for (int nt = 0; nt < 8; nt++) {
            int brow = (nb + nt) * 8 + r8;
            uint32_t b0, b1;
            ldsm_x2(WshB + brow * 256 + ((bch ^ (brow & 7)) << 4), b0, b1);
            mma16816(c[nt], a0, a1, a2, a3, b0, b1);
        }
    }

    int r1 = bn + mb + (lane >> 2);
    int r2 = r1 + 8;
    float s1 = (r1 < NN) ? g_dinv[r1] : 0.f;
    float s2 = (r2 < NN) ? g_dinv[r2] : 0.f;
    #pragma unroll
    for (int nt = 0; nt < 8; nt++) {
        int col = (nb + nt) * 8 + (lane & 3) * 2;
        if (r1 < NN)
            *(__half2*)&g_xw[(size_t)r1 * HID + col] = __floats2half2_rn(c[nt][0] * s1, c[nt][1] * s1);
        if (r2 < NN)
            *(__half2*)&g_xw[(size_t)r2 * HID + col] = __floats2half2_rn(c[nt][2] * s2, c[nt][3] * s2);
    }
}

// ---------------- aggregation (hidden layers), 4-wide MLP ----------------
// g_h[d] = relu( dinv[d] * ( xw[d] + sum_e xw[s] ) + b ), xw scaled by dinv[row]
__global__ void k_agg_h(const float* __restrict__ bias) {
    int wid = (blockIdx.x * blockDim.x + threadIdx.x) >> 5;
    int lane = threadIdx.x & 31;
    if (wid >= NN) return;
    int r = g_rowptr[wid], e = g_rowptr[wid + 1];
    uint2 v0 = *(const uint2*)&g_xw[(size_t)wid * HID + lane * 4];  // self loop
    float2 f0 = __half22float2(*(__half2*)&v0.x);
    float2 f1 = __half22float2(*(__half2*)&v0.y);
    float4 acc = make_float4(f0.x, f0.y, f1.x, f1.y);
    int j = r;
    for (; j + 4 <= e; j += 4) {
        int s0 = g_col[j], s1 = g_col[j + 1], s2 = g_col[j + 2], s3 = g_col[j + 3];
        uint2 w0 = *(const uint2*)&g_xw[(size_t)s0 * HID + lane * 4];
        uint2 w1 = *(const uint2*)&g_xw[(size_t)s1 * HID + lane * 4];
        uint2 w2 = *(const uint2*)&g_xw[(size_t)s2 * HID + lane * 4];
        uint2 w3 = *(const uint2*)&g_xw[(size_t)s3 * HID + lane * 4];
        float2 a0 = __half22float2(*(__half2*)&w0.x), a1 = __half22float2(*(__half2*)&w0.y);
        float2 b0 = __half22float2(*(__half2*)&w1.x), b1 = __half22float2(*(__half2*)&w1.y);
        float2 c0 = __half22float2(*(__half2*)&w2.x), c1 = __half22float2(*(__half2*)&w2.y);
        float2 d0 = __half22float2(*(__half2*)&w3.x), d1 = __half22float2(*(__half2*)&w3.y);
        acc.x += (a0.x + b0.x) + (c0.x + d0.x);
        acc.y += (a0.y + b0.y) + (c0.y + d0.y);
        acc.z += (a1.x + b1.x) + (c1.x + d1.x);
        acc.w += (a1.y + b1.y) + (c1.y + d1.y);
    }
    for (; j < e; j++) {
        int s = g_col[j];
        uint2 v = *(const uint2*)&g_xw[(size_t)s * HID + lane * 4];
        float2 a0 = __half22float2(*(__half2*)&v.x);
        float2 a1 = __half22float2(*(__half2*)&v.y);
        acc.x += a0.x; acc.y += a0.y; acc.z += a1.x; acc.w += a1.y;
    }
    float dn = g_dinv[wid];
    float4 b = *(const float4*)&bias[lane * 4];
    float ox = fmaxf(acc.x * dn + b.x, 0.f), oy = fmaxf(acc.y * dn + b.y, 0.f);
    float oz = fmaxf(acc.z * dn + b.z, 0.f), ow = fmaxf(acc.w * dn + b.w, 0.f);
    __half2* p = (__half2*)&g_h[(size_t)wid * HID + lane * 4];
    p[0] = __floats2half2_rn(ox, oy);
    p[1] = __floats2half2_rn(oz, ow);
}

// ---------------- mean-pool + output head ----------------
__global__ void k_pool(const float* __restrict__ Wout, const float* __restrict__ bout,
                       float* __restrict__ out) {
    int gg = blockIdx.x;
    int t = threadIdx.x;  // 128
    int st = g_gstart[gg], en = g_gstart[gg + 1];
    float acc = 0.f;
    for (int n = st; n < en; n++) acc += __half2float(g_h[(size_t)n * HID + t]);
    __shared__ float pooled[HID];
    float cnt = (float)(en - st);
    if (cnt < 1.f) cnt = 1.f;
    pooled[t] = acc / cnt;
    __syncthreads();
    if (t < OUTF) {
        float o = bout[t];
        #pragma unroll 8
        for (int k = 0; k < HID; k++) o += pooled[k] * Wout[k * OUTF + t];
        out[(size_t)gg * OUTF + t] = o;
    }
}

// ---------------- launcher ----------------
extern "C" void kernel_launch(void* const* d_in, const int* in_sizes, int n_in,
                              void* d_out, int out_size) {
    const float* x     = (const float*)d_in[0];
    const void*  ei    = d_in[1];
    const void*  batch = d_in[2];
    const float* W1 = (const float*)d_in[3];  const float* b1 = (const float*)d_in[4];
    const float* W2 = (const float*)d_in[5];  const float* b2 = (const float*)d_in[6];
    const float* W3 = (const float*)d_in[7];  const float* b3 = (const float*)d_in[8];
    const float* Wout = (const float*)d_in[9]; const float* bout = (const float*)d_in[10];
    float* out = (float*)d_out;

    const int agg_blocks = (NN + 7) / 8;     // warp per node
    const int mma_blocks = (NN + 63) / 64;

    k_pre<<<PRE_ZBLK + PRE_WBLK, 256>>>(W2, W3, (const int*)ei);
    k_count<<<(NE + NN + 255) / 256, 256>>>(ei, batch);
    k_scan_part<<<NSCAN_BLK, 256>>>();
    k_scan_mid<<<2, 512>>>();
    k_scan_final<<<NSCAN_BLK, 256>>>(x);
    k_scatter<<<(NE + 255) / 256, 256>>>(ei);

    // layer 1 (fused agg + gemm)
    k_aggx_gemm1<<<(NN + 63) / 64, 256>>>(W1, b1);
    // layer 2
    k_gemm_mma<<<mma_blocks, 256>>>(0);
    k_agg_h<<<agg_blocks, 256>>>(b2);
    // layer 3
    k_gemm_mma<<<mma_blocks, 256>>>(1);
    k_agg_h<<<agg_blocks, 256>>>(b3);

    // pool + head
    k_pool<<<NG, HID>>>(Wout, bout, out);
}